// round 15
// baseline (speedup 1.0000x reference)
#include <cuda_runtime.h>
#include <cuda_fp16.h>
#include <cstdint>

#define NH 64
#define NK 64
#define TM 128          // rows per CTA (pass1)
#define P1T 128
#define P2T 256
#define STRD 68         // fp32 stage row stride (floats)

// word (4B) offsets in dynamic smem
#define WA   0          // A half-tile: 128 rows x 32 words (64 halfs), swizzled
#define WB   4096       // B half-tile: 64 rows x 32 words
#define WSTG 0          // fp32 Q stage (128 x 68) overlaps A/B after GEMM
#define WZ2  8704       // 128 floats
#define WC2  8832       // 64
#define WCOL 8896       // 64
#define SMEM_WORDS 8960
#define SMEM_BYTES (SMEM_WORDS * 4)   // 35840

__device__ float g_colsum[NK];
__device__ unsigned g_done;

__device__ __forceinline__ void mma_f16(float* d, uint32_t a0, uint32_t a1,
                                        uint32_t a2, uint32_t a3,
                                        uint32_t b0, uint32_t b1) {
    asm volatile(
        "mma.sync.aligned.m16n8k16.row.col.f32.f16.f16.f32 "
        "{%0,%1,%2,%3}, {%4,%5,%6,%7}, {%8,%9}, {%0,%1,%2,%3};"
        : "+f"(d[0]), "+f"(d[1]), "+f"(d[2]), "+f"(d[3])
        : "r"(a0), "r"(a1), "r"(a2), "r"(a3), "r"(b0), "r"(b1));
}
__device__ __forceinline__ float sqrt_ap(float x) {
    float r; asm("sqrt.approx.f32 %0, %1;" : "=f"(r) : "f"(x)); return r;
}
__device__ __forceinline__ float rcp_ap(float x) {
    float r; asm("rcp.approx.f32 %0, %1;" : "=f"(r) : "f"(x)); return r;
}
__device__ __forceinline__ uint32_t f2h2(float a, float b) {
    __half2 h = __floats2half2_rn(a, b);
    return *reinterpret_cast<uint32_t*>(&h);
}
// swizzled word offset for half tiles: row r, 16B chunk j (0..7), word w (0..3)
__device__ __forceinline__ uint32_t swz(int r, int j, int w) {
    return r * 32 + ((j ^ (r & 7)) << 2) + w;
}

// ---------------------------------------------------------------------------
// Pass 1: Q = rownorm(1/(1+sqrt(max(||z||^2+||c||^2-2 z.c, 0)))) via fp16
// m16n8k16 mma.sync. 4 warps x (32 rows x 64 cols), TM=128 rows/CTA,
// 6 CTAs/SM (vs 5 in R14) for deeper cross-CTA phase interleaving.
// ---------------------------------------------------------------------------
__global__ void __launch_bounds__(P1T, 6)
k_pass1(const float* __restrict__ z, const float* __restrict__ c,
        float* __restrict__ Q) {
    extern __shared__ __align__(16) uint32_t smw[];
    float* smf = (float*)smw;
    const int t = threadIdx.x;
    const int warp = t >> 5, lane = t & 31;
    const int g = lane >> 2, tig = lane & 3;

    const long long row0 = (long long)blockIdx.x * TM;

    // --- Stage z (128x64 fp32 -> fp16, swizzled), coalesced LDG.128 ---
    {
        const float4* zg = (const float4*)(z + row0 * NH);
#pragma unroll
        for (int k = 0; k < 16; ++k) {
            int i = t + k * P1T;
            float4 v = zg[i];
            int r = i >> 4, c4 = i & 15;
            uint32_t dst = WA + swz(r, c4 >> 1, 2 * (c4 & 1));
            *(uint2*)(smw + dst) = make_uint2(f2h2(v.x, v.y), f2h2(v.z, v.w));
        }
        const float4* cg = (const float4*)c;
#pragma unroll
        for (int k = 0; k < 8; ++k) {
            int i = t + k * P1T;
            float4 v = cg[i];
            int r = i >> 4, c4 = i & 15;
            uint32_t dst = WB + swz(r, c4 >> 1, 2 * (c4 & 1));
            *(uint2*)(smw + dst) = make_uint2(f2h2(v.x, v.y), f2h2(v.z, v.w));
        }
    }
    if (t < NK) smf[WCOL + t] = 0.f;
    __syncthreads();

    // --- ||z_r||^2 (threads 0..127) and ||c_n||^2 (threads 0..63) from tiles
    {
        float s = 0.f;
#pragma unroll
        for (int j = 0; j < 8; ++j) {
            uint4 q = *(const uint4*)(smw + WA + swz(t, j, 0));
            float2 f;
            f = __half22float2(*(__half2*)&q.x); s = fmaf(f.x,f.x,s); s = fmaf(f.y,f.y,s);
            f = __half22float2(*(__half2*)&q.y); s = fmaf(f.x,f.x,s); s = fmaf(f.y,f.y,s);
            f = __half22float2(*(__half2*)&q.z); s = fmaf(f.x,f.x,s); s = fmaf(f.y,f.y,s);
            f = __half22float2(*(__half2*)&q.w); s = fmaf(f.x,f.x,s); s = fmaf(f.y,f.y,s);
        }
        smf[WZ2 + t] = s;
        if (t < NK) {
            float sc = 0.f;
#pragma unroll
            for (int j = 0; j < 8; ++j) {
                uint4 q = *(const uint4*)(smw + WB + swz(t, j, 0));
                float2 f;
                f = __half22float2(*(__half2*)&q.x); sc = fmaf(f.x,f.x,sc); sc = fmaf(f.y,f.y,sc);
                f = __half22float2(*(__half2*)&q.y); sc = fmaf(f.x,f.x,sc); sc = fmaf(f.y,f.y,sc);
                f = __half22float2(*(__half2*)&q.z); sc = fmaf(f.x,f.x,sc); sc = fmaf(f.y,f.y,sc);
                f = __half22float2(*(__half2*)&q.w); sc = fmaf(f.x,f.x,sc); sc = fmaf(f.y,f.y,sc);
            }
            smf[WC2 + t] = sc;
        }
    }
    __syncthreads();

    // --- GEMM: warp w owns rows [w*32, w*32+32); 2 M-tiles x 8 N-tiles,
    //     4 K-steps of 16.
    float d[8][2][4];
#pragma unroll
    for (int nt = 0; nt < 8; ++nt)
#pragma unroll
        for (int mt = 0; mt < 2; ++mt)
#pragma unroll
            for (int j = 0; j < 4; ++j) d[nt][mt][j] = 0.f;

    const int rowbase = warp * 32;

#pragma unroll
    for (int ks = 0; ks < 4; ++ks) {
        const int ch = (2 * ks) ^ g;   // swizzled chunk for this lane's rows
        uint32_t a[2][4];
#pragma unroll
        for (int mt = 0; mt < 2; ++mt) {
            uint32_t base = WA + (rowbase + mt * 16 + g) * 32 + (ch << 2) + tig;
            a[mt][0] = smw[base];
            a[mt][1] = smw[base + 256];        // row + 8
            a[mt][2] = smw[base ^ 4];          // second k-half
            a[mt][3] = smw[(base + 256) ^ 4];
        }
#pragma unroll
        for (int nt = 0; nt < 8; ++nt) {
            uint32_t bb = WB + (nt * 8 + g) * 32 + (ch << 2) + tig;
            uint32_t b0 = smw[bb];
            uint32_t b1 = smw[bb ^ 4];
#pragma unroll
            for (int mt = 0; mt < 2; ++mt)
                mma_f16(d[nt][mt], a[mt][0], a[mt][1], a[mt][2], a[mt][3],
                        b0, b1);
        }
    }

    // --- Epilogue (in place). Thread owns rows rowbase + mt*16 + hr*8 + g,
    //     cols nt*8 + 2*tig + {0,1}.
    float z2r[4];
    z2r[0] = smf[WZ2 + rowbase + g];
    z2r[1] = smf[WZ2 + rowbase + g + 8];
    z2r[2] = smf[WZ2 + rowbase + g + 16];
    z2r[3] = smf[WZ2 + rowbase + g + 24];

    float rs[4] = {0.f, 0.f, 0.f, 0.f};
#pragma unroll
    for (int nt = 0; nt < 8; ++nt) {
        float c2a = smf[WC2 + nt * 8 + 2 * tig];
        float c2b = smf[WC2 + nt * 8 + 2 * tig + 1];
#pragma unroll
        for (int mt = 0; mt < 2; ++mt) {
#pragma unroll
            for (int hr = 0; hr < 2; ++hr) {
                int r = mt * 2 + hr;
                float da = fmaf(-2.f, d[nt][mt][hr * 2],     z2r[r] + c2a);
                float db = fmaf(-2.f, d[nt][mt][hr * 2 + 1], z2r[r] + c2b);
                float qa = rcp_ap(1.f + sqrt_ap(fmaxf(da, 0.f)));
                float qb = rcp_ap(1.f + sqrt_ap(fmaxf(db, 0.f)));
                d[nt][mt][hr * 2]     = qa;
                d[nt][mt][hr * 2 + 1] = qb;
                rs[r] += qa + qb;
            }
        }
    }
#pragma unroll
    for (int r = 0; r < 4; ++r) {
        rs[r] += __shfl_xor_sync(0xffffffffu, rs[r], 1);
        rs[r] += __shfl_xor_sync(0xffffffffu, rs[r], 2);
        rs[r] = rcp_ap(rs[r]);
    }

    __syncthreads();   // A/B tiles dead -> reuse smem as fp32 Q stage

    float* stage = smf + WSTG;
#pragma unroll
    for (int nt = 0; nt < 8; ++nt) {
        float csa = 0.f, csb = 0.f;
#pragma unroll
        for (int mt = 0; mt < 2; ++mt) {
#pragma unroll
            for (int hr = 0; hr < 2; ++hr) {
                int r = mt * 2 + hr;
                float qa = d[nt][mt][hr * 2] * rs[r];
                float qb = d[nt][mt][hr * 2 + 1] * rs[r];
                csa += qa;
                csb += qb;
                float2 v = {qa, qb};
                *(float2*)(stage + (rowbase + mt * 16 + hr * 8 + g) * STRD +
                           nt * 8 + 2 * tig) = v;
            }
        }
        d[nt][0][0] = csa;
        d[nt][0][1] = csb;
    }
#pragma unroll
    for (int nt = 0; nt < 8; ++nt) {
#pragma unroll
        for (int j = 0; j < 2; ++j) {
            d[nt][0][j] += __shfl_xor_sync(0xffffffffu, d[nt][0][j], 4);
            d[nt][0][j] += __shfl_xor_sync(0xffffffffu, d[nt][0][j], 8);
            d[nt][0][j] += __shfl_xor_sync(0xffffffffu, d[nt][0][j], 16);
        }
    }
    if (g == 0) {
#pragma unroll
        for (int nt = 0; nt < 8; ++nt) {
            atomicAdd(&smf[WCOL + nt * 8 + 2 * tig], d[nt][0][0]);
            atomicAdd(&smf[WCOL + nt * 8 + 2 * tig + 1], d[nt][0][1]);
        }
    }
    __syncthreads();

    // Fully coalesced Q writeback.
    float4* out = (float4*)(Q + row0 * NH);
#pragma unroll 4
    for (int i = t; i < TM * 16; i += P1T) {
        int rr = i >> 4, cc = i & 15;
        out[i] = *(const float4*)(stage + rr * STRD + cc * 4);
    }
    if (t < NK) atomicAdd(&g_colsum[t], smf[WCOL + t]);
}

// ---------------------------------------------------------------------------
// Pass 2: P = rownorm(Q^2 / colsum). 8 lanes per row, interleaved float4
// ownership -> every LDG/STG.128 covers whole 128B lines (minimal L1
// wavefronts; proven R14 config). Last block re-zeroes colsum + ticket.
// ---------------------------------------------------------------------------
__global__ void __launch_bounds__(P2T)
k_pass2(const float* __restrict__ Q, float* __restrict__ P) {
    __shared__ float s_ic[NK];
    const int t = threadIdx.x;
    if (t < NK) s_ic[t] = rcp_ap(g_colsum[t]);
    __syncthreads();

    if (t == 0) {
        unsigned old = atomicAdd(&g_done, 1u);
        if (old == gridDim.x - 1) {
#pragma unroll
            for (int k = 0; k < NK; ++k) g_colsum[k] = 0.f;
            g_done = 0;
            __threadfence();
        }
    }

    const int warp = t >> 5, lane = t & 31;
    const int rsub = lane >> 3;     // row within the warp's 4-row group
    const int p8 = lane & 7;        // position within the 8-lane row group

    const long long row = (long long)blockIdx.x * 32 + warp * 4 + rsub;
    const float4* __restrict__ qr = (const float4*)(Q + row * NH);

    float4 ic0 = *(const float4*)(s_ic + 4 * p8);        // cols 4*p8..+3
    float4 ic1 = *(const float4*)(s_ic + 4 * p8 + 32);   // cols 4*p8+32..+3

    float4 v0 = qr[p8];        // fully coalesced: 8 lanes cover one 128B line
    float4 v1 = qr[p8 + 8];

    float4 q0, q1;
    q0.x = v0.x * v0.x * ic0.x;
    q0.y = v0.y * v0.y * ic0.y;
    q0.z = v0.z * v0.z * ic0.z;
    q0.w = v0.w * v0.w * ic0.w;
    q1.x = v1.x * v1.x * ic1.x;
    q1.y = v1.y * v1.y * ic1.y;
    q1.z = v1.z * v1.z * ic1.z;
    q1.w = v1.w * v1.w * ic1.w;

    float rs = ((q0.x + q0.y) + (q0.z + q0.w)) +
               ((q1.x + q1.y) + (q1.z + q1.w));
    rs += __shfl_xor_sync(0xffffffffu, rs, 1);
    rs += __shfl_xor_sync(0xffffffffu, rs, 2);
    rs += __shfl_xor_sync(0xffffffffu, rs, 4);
    const float inv = rcp_ap(rs);

    float4* __restrict__ po = (float4*)(P + row * NH);
    float4 o0, o1;
    o0.x = q0.x * inv; o0.y = q0.y * inv;
    o0.z = q0.z * inv; o0.w = q0.w * inv;
    o1.x = q1.x * inv; o1.y = q1.y * inv;
    o1.z = q1.z * inv; o1.w = q1.w * inv;
    po[p8] = o0;
    po[p8 + 8] = o1;
}

// ---------------------------------------------------------------------------
extern "C" void kernel_launch(void* const* d_in, const int* in_sizes, int n_in,
                              void* d_out, int out_size) {
    const float* z = (const float*)d_in[0];  // (BS, 64)
    const float* c = (const float*)d_in[1];  // (64, 64)
    const long long n_rows = (long long)in_sizes[0] / NH;

    float* Q = (float*)d_out;
    float* P = Q + n_rows * NK;

    static bool attr_set = false;
    if (!attr_set) {
        cudaFuncSetAttribute(k_pass1, cudaFuncAttributeMaxDynamicSharedMemorySize,
                             SMEM_BYTES);
        attr_set = true;
    }

    k_pass1<<<(int)(n_rows / TM), P1T, SMEM_BYTES>>>(z, c, Q);
    k_pass2<<<(int)(n_rows / 32), P2T>>>(Q, P);
}

// round 16
// speedup vs baseline: 1.5093x; 1.5093x over previous
#include <cuda_runtime.h>
#include <cuda_fp16.h>
#include <cstdint>

#define NH 64
#define NK 64
#define TM 128          // rows per CTA (pass1)
#define P1T 128
#define P2T 256
#define STRD 68         // fp32 stage row stride (floats)

// word (4B) offsets in dynamic smem
#define WA   0          // A half-tile: 128 rows x 32 words (64 halfs), swizzled
#define WB   4096       // B half-tile: 64 rows x 32 words
#define WSTG 0          // fp32 Q stage (128 x 68) overlaps A/B after GEMM
#define WZ2  8704       // 128 floats
#define WC2  8832       // 64
#define WCOL 8896       // 64
#define SMEM_WORDS 8960
#define SMEM_BYTES (SMEM_WORDS * 4)   // 35840

__device__ float g_colsum[NK];
__device__ unsigned g_done;

__device__ __forceinline__ void mma_f16(float* d, uint32_t a0, uint32_t a1,
                                        uint32_t a2, uint32_t a3,
                                        uint32_t b0, uint32_t b1) {
    asm volatile(
        "mma.sync.aligned.m16n8k16.row.col.f32.f16.f16.f32 "
        "{%0,%1,%2,%3}, {%4,%5,%6,%7}, {%8,%9}, {%0,%1,%2,%3};"
        : "+f"(d[0]), "+f"(d[1]), "+f"(d[2]), "+f"(d[3])
        : "r"(a0), "r"(a1), "r"(a2), "r"(a3), "r"(b0), "r"(b1));
}
__device__ __forceinline__ float sqrt_ap(float x) {
    float r; asm("sqrt.approx.f32 %0, %1;" : "=f"(r) : "f"(x)); return r;
}
__device__ __forceinline__ float rcp_ap(float x) {
    float r; asm("rcp.approx.f32 %0, %1;" : "=f"(r) : "f"(x)); return r;
}
__device__ __forceinline__ uint32_t f2h2(float a, float b) {
    __half2 h = __floats2half2_rn(a, b);
    return *reinterpret_cast<uint32_t*>(&h);
}
// swizzled word offset for half tiles: row r, 16B chunk j (0..7), word w (0..3)
__device__ __forceinline__ uint32_t swz(int r, int j, int w) {
    return r * 32 + ((j ^ (r & 7)) << 2) + w;
}

// ---------------------------------------------------------------------------
// Pass 1: Q = rownorm(1/(1+sqrt(max(||z||^2+||c||^2-2 z.c, 0)))) via fp16
// m16n8k16 mma.sync. 4 warps x (32 rows x 64 cols), TM=128 rows/CTA,
// 5 CTAs/SM. Q writeback is WARP-LOCAL (each warp stores the rows it staged)
// so stores issue per-warp after __syncwarp instead of a CTA-wide barrier.
// ---------------------------------------------------------------------------
__global__ void __launch_bounds__(P1T, 5)
k_pass1(const float* __restrict__ z, const float* __restrict__ c,
        float* __restrict__ Q) {
    extern __shared__ __align__(16) uint32_t smw[];
    float* smf = (float*)smw;
    const int t = threadIdx.x;
    const int warp = t >> 5, lane = t & 31;
    const int g = lane >> 2, tig = lane & 3;

    const long long row0 = (long long)blockIdx.x * TM;

    // --- Stage z (128x64 fp32 -> fp16, swizzled), coalesced LDG.128 ---
    {
        const float4* zg = (const float4*)(z + row0 * NH);
#pragma unroll
        for (int k = 0; k < 16; ++k) {
            int i = t + k * P1T;
            float4 v = zg[i];
            int r = i >> 4, c4 = i & 15;
            uint32_t dst = WA + swz(r, c4 >> 1, 2 * (c4 & 1));
            *(uint2*)(smw + dst) = make_uint2(f2h2(v.x, v.y), f2h2(v.z, v.w));
        }
        const float4* cg = (const float4*)c;
#pragma unroll
        for (int k = 0; k < 8; ++k) {
            int i = t + k * P1T;
            float4 v = cg[i];
            int r = i >> 4, c4 = i & 15;
            uint32_t dst = WB + swz(r, c4 >> 1, 2 * (c4 & 1));
            *(uint2*)(smw + dst) = make_uint2(f2h2(v.x, v.y), f2h2(v.z, v.w));
        }
    }
    if (t < NK) smf[WCOL + t] = 0.f;
    __syncthreads();

    // --- ||z_r||^2 (threads 0..127) and ||c_n||^2 (threads 0..63) from tiles
    {
        float s = 0.f;
#pragma unroll
        for (int j = 0; j < 8; ++j) {
            uint4 q = *(const uint4*)(smw + WA + swz(t, j, 0));
            float2 f;
            f = __half22float2(*(__half2*)&q.x); s = fmaf(f.x,f.x,s); s = fmaf(f.y,f.y,s);
            f = __half22float2(*(__half2*)&q.y); s = fmaf(f.x,f.x,s); s = fmaf(f.y,f.y,s);
            f = __half22float2(*(__half2*)&q.z); s = fmaf(f.x,f.x,s); s = fmaf(f.y,f.y,s);
            f = __half22float2(*(__half2*)&q.w); s = fmaf(f.x,f.x,s); s = fmaf(f.y,f.y,s);
        }
        smf[WZ2 + t] = s;
        if (t < NK) {
            float sc = 0.f;
#pragma unroll
            for (int j = 0; j < 8; ++j) {
                uint4 q = *(const uint4*)(smw + WB + swz(t, j, 0));
                float2 f;
                f = __half22float2(*(__half2*)&q.x); sc = fmaf(f.x,f.x,sc); sc = fmaf(f.y,f.y,sc);
                f = __half22float2(*(__half2*)&q.y); sc = fmaf(f.x,f.x,sc); sc = fmaf(f.y,f.y,sc);
                f = __half22float2(*(__half2*)&q.z); sc = fmaf(f.x,f.x,sc); sc = fmaf(f.y,f.y,sc);
                f = __half22float2(*(__half2*)&q.w); sc = fmaf(f.x,f.x,sc); sc = fmaf(f.y,f.y,sc);
            }
            smf[WC2 + t] = sc;
        }
    }
    __syncthreads();

    // --- GEMM: warp w owns rows [w*32, w*32+32); 2 M-tiles x 8 N-tiles,
    //     4 K-steps of 16.
    float d[8][2][4];
#pragma unroll
    for (int nt = 0; nt < 8; ++nt)
#pragma unroll
        for (int mt = 0; mt < 2; ++mt)
#pragma unroll
            for (int j = 0; j < 4; ++j) d[nt][mt][j] = 0.f;

    const int rowbase = warp * 32;

#pragma unroll
    for (int ks = 0; ks < 4; ++ks) {
        const int ch = (2 * ks) ^ g;   // swizzled chunk for this lane's rows
        uint32_t a[2][4];
#pragma unroll
        for (int mt = 0; mt < 2; ++mt) {
            uint32_t base = WA + (rowbase + mt * 16 + g) * 32 + (ch << 2) + tig;
            a[mt][0] = smw[base];
            a[mt][1] = smw[base + 256];        // row + 8
            a[mt][2] = smw[base ^ 4];          // second k-half
            a[mt][3] = smw[(base + 256) ^ 4];
        }
#pragma unroll
        for (int nt = 0; nt < 8; ++nt) {
            uint32_t bb = WB + (nt * 8 + g) * 32 + (ch << 2) + tig;
            uint32_t b0 = smw[bb];
            uint32_t b1 = smw[bb ^ 4];
#pragma unroll
            for (int mt = 0; mt < 2; ++mt)
                mma_f16(d[nt][mt], a[mt][0], a[mt][1], a[mt][2], a[mt][3],
                        b0, b1);
        }
    }

    // --- Epilogue (in place). Thread owns rows rowbase + mt*16 + hr*8 + g,
    //     cols nt*8 + 2*tig + {0,1}.
    float z2r[4];
    z2r[0] = smf[WZ2 + rowbase + g];
    z2r[1] = smf[WZ2 + rowbase + g + 8];
    z2r[2] = smf[WZ2 + rowbase + g + 16];
    z2r[3] = smf[WZ2 + rowbase + g + 24];

    float rs[4] = {0.f, 0.f, 0.f, 0.f};
#pragma unroll
    for (int nt = 0; nt < 8; ++nt) {
        float c2a = smf[WC2 + nt * 8 + 2 * tig];
        float c2b = smf[WC2 + nt * 8 + 2 * tig + 1];
#pragma unroll
        for (int mt = 0; mt < 2; ++mt) {
#pragma unroll
            for (int hr = 0; hr < 2; ++hr) {
                int r = mt * 2 + hr;
                float da = fmaf(-2.f, d[nt][mt][hr * 2],     z2r[r] + c2a);
                float db = fmaf(-2.f, d[nt][mt][hr * 2 + 1], z2r[r] + c2b);
                float qa = rcp_ap(1.f + sqrt_ap(fmaxf(da, 0.f)));
                float qb = rcp_ap(1.f + sqrt_ap(fmaxf(db, 0.f)));
                d[nt][mt][hr * 2]     = qa;
                d[nt][mt][hr * 2 + 1] = qb;
                rs[r] += qa + qb;
            }
        }
    }
#pragma unroll
    for (int r = 0; r < 4; ++r) {
        rs[r] += __shfl_xor_sync(0xffffffffu, rs[r], 1);
        rs[r] += __shfl_xor_sync(0xffffffffu, rs[r], 2);
        rs[r] = rcp_ap(rs[r]);
    }

    __syncthreads();   // A/B tiles dead -> reuse smem as fp32 Q stage

    // Normalize; stage own warp's rows; fold colsum partials.
    float* stage = smf + WSTG;
#pragma unroll
    for (int nt = 0; nt < 8; ++nt) {
        float csa = 0.f, csb = 0.f;
#pragma unroll
        for (int mt = 0; mt < 2; ++mt) {
#pragma unroll
            for (int hr = 0; hr < 2; ++hr) {
                int r = mt * 2 + hr;
                float qa = d[nt][mt][hr * 2] * rs[r];
                float qb = d[nt][mt][hr * 2 + 1] * rs[r];
                csa += qa;
                csb += qb;
                float2 v = {qa, qb};
                *(float2*)(stage + (rowbase + mt * 16 + hr * 8 + g) * STRD +
                           nt * 8 + 2 * tig) = v;
            }
        }
        d[nt][0][0] = csa;
        d[nt][0][1] = csb;
    }
#pragma unroll
    for (int nt = 0; nt < 8; ++nt) {
#pragma unroll
        for (int j = 0; j < 2; ++j) {
            d[nt][0][j] += __shfl_xor_sync(0xffffffffu, d[nt][0][j], 4);
            d[nt][0][j] += __shfl_xor_sync(0xffffffffu, d[nt][0][j], 8);
            d[nt][0][j] += __shfl_xor_sync(0xffffffffu, d[nt][0][j], 16);
        }
    }
    if (g == 0) {
#pragma unroll
        for (int nt = 0; nt < 8; ++nt) {
            atomicAdd(&smf[WCOL + nt * 8 + 2 * tig], d[nt][0][0]);
            atomicAdd(&smf[WCOL + nt * 8 + 2 * tig + 1], d[nt][0][1]);
        }
    }
    __syncwarp();      // own warp's staged rows visible -> store immediately

    // WARP-LOCAL coalesced Q writeback: warp w stores rows [w*32, w*32+32).
    // i = warp*512 + lane + k*32 -> 512B contiguous per warp-instruction.
    float4* out = (float4*)(Q + row0 * NH);
#pragma unroll
    for (int k = 0; k < 16; ++k) {
        int i = warp * 512 + lane + k * 32;
        int rr = i >> 4, cc = i & 15;
        out[i] = *(const float4*)(stage + rr * STRD + cc * 4);
    }

    __syncthreads();   // all warps' smem colsum atomics complete
    if (t < NK) atomicAdd(&g_colsum[t], smf[WCOL + t]);
}

// ---------------------------------------------------------------------------
// Pass 2: P = rownorm(Q^2 / colsum). 8 lanes per row, interleaved float4
// ownership -> every LDG/STG.128 covers whole 128B lines (minimal L1
// wavefronts; proven R14 config). Last block re-zeroes colsum + ticket.
// ---------------------------------------------------------------------------
__global__ void __launch_bounds__(P2T)
k_pass2(const float* __restrict__ Q, float* __restrict__ P) {
    __shared__ float s_ic[NK];
    const int t = threadIdx.x;
    if (t < NK) s_ic[t] = rcp_ap(g_colsum[t]);
    __syncthreads();

    if (t == 0) {
        unsigned old = atomicAdd(&g_done, 1u);
        if (old == gridDim.x - 1) {
#pragma unroll
            for (int k = 0; k < NK; ++k) g_colsum[k] = 0.f;
            g_done = 0;
            __threadfence();
        }
    }

    const int warp = t >> 5, lane = t & 31;
    const int rsub = lane >> 3;     // row within the warp's 4-row group
    const int p8 = lane & 7;        // position within the 8-lane row group

    const long long row = (long long)blockIdx.x * 32 + warp * 4 + rsub;
    const float4* __restrict__ qr = (const float4*)(Q + row * NH);

    float4 ic0 = *(const float4*)(s_ic + 4 * p8);        // cols 4*p8..+3
    float4 ic1 = *(const float4*)(s_ic + 4 * p8 + 32);   // cols 4*p8+32..+3

    float4 v0 = qr[p8];        // fully coalesced: 8 lanes cover one 128B line
    float4 v1 = qr[p8 + 8];

    float4 q0, q1;
    q0.x = v0.x * v0.x * ic0.x;
    q0.y = v0.y * v0.y * ic0.y;
    q0.z = v0.z * v0.z * ic0.z;
    q0.w = v0.w * v0.w * ic0.w;
    q1.x = v1.x * v1.x * ic1.x;
    q1.y = v1.y * v1.y * ic1.y;
    q1.z = v1.z * v1.z * ic1.z;
    q1.w = v1.w * v1.w * ic1.w;

    float rs = ((q0.x + q0.y) + (q0.z + q0.w)) +
               ((q1.x + q1.y) + (q1.z + q1.w));
    rs += __shfl_xor_sync(0xffffffffu, rs, 1);
    rs += __shfl_xor_sync(0xffffffffu, rs, 2);
    rs += __shfl_xor_sync(0xffffffffu, rs, 4);
    const float inv = rcp_ap(rs);

    float4* __restrict__ po = (float4*)(P + row * NH);
    float4 o0, o1;
    o0.x = q0.x * inv; o0.y = q0.y * inv;
    o0.z = q0.z * inv; o0.w = q0.w * inv;
    o1.x = q1.x * inv; o1.y = q1.y * inv;
    o1.z = q1.z * inv; o1.w = q1.w * inv;
    po[p8] = o0;
    po[p8 + 8] = o1;
}

// ---------------------------------------------------------------------------
extern "C" void kernel_launch(void* const* d_in, const int* in_sizes, int n_in,
                              void* d_out, int out_size) {
    const float* z = (const float*)d_in[0];  // (BS, 64)
    const float* c = (const float*)d_in[1];  // (64, 64)
    const long long n_rows = (long long)in_sizes[0] / NH;

    float* Q = (float*)d_out;
    float* P = Q + n_rows * NK;

    static bool attr_set = false;
    if (!attr_set) {
        cudaFuncSetAttribute(k_pass1, cudaFuncAttributeMaxDynamicSharedMemorySize,
                             SMEM_BYTES);
        attr_set = true;
    }

    k_pass1<<<(int)(n_rows / TM), P1T, SMEM_BYTES>>>(z, c, Q);
    k_pass2<<<(int)(n_rows / 32), P2T>>>(Q, P);
}

// round 17
// speedup vs baseline: 1.5103x; 1.0007x over previous
#include <cuda_runtime.h>
#include <cuda_fp16.h>
#include <cstdint>

#define NH 64
#define NK 64
#define TM 128          // rows per CTA (pass1)
#define P1T 128
#define P2T 256
#define STRD 68         // fp32 stage row stride (floats)

// word (4B) offsets in dynamic smem
#define WA   0          // A half-tile: 128 rows x 32 words (64 halfs), swizzled
#define WB   4096       // B half-tile: 64 rows x 32 words
#define WSTG 0          // fp32 Q stage (128 x 68) overlaps A/B after GEMM
#define WZ2  8704       // 128 floats
#define WC2  8832       // 64
#define WCOL 8896       // 64
#define SMEM_WORDS 8960
#define SMEM_BYTES (SMEM_WORDS * 4)   // 35840

__device__ float g_colsum[NK];
__device__ unsigned g_done;

__device__ __forceinline__ void mma_f16(float* d, uint32_t a0, uint32_t a1,
                                        uint32_t a2, uint32_t a3,
                                        uint32_t b0, uint32_t b1) {
    asm volatile(
        "mma.sync.aligned.m16n8k16.row.col.f32.f16.f16.f32 "
        "{%0,%1,%2,%3}, {%4,%5,%6,%7}, {%8,%9}, {%0,%1,%2,%3};"
        : "+f"(d[0]), "+f"(d[1]), "+f"(d[2]), "+f"(d[3])
        : "r"(a0), "r"(a1), "r"(a2), "r"(a3), "r"(b0), "r"(b1));
}
__device__ __forceinline__ void ldsm_x4(uint32_t& r0, uint32_t& r1,
                                        uint32_t& r2, uint32_t& r3,
                                        uint32_t addr) {
    asm volatile(
        "ldmatrix.sync.aligned.m8n8.x4.shared.b16 {%0,%1,%2,%3}, [%4];"
        : "=r"(r0), "=r"(r1), "=r"(r2), "=r"(r3) : "r"(addr));
}
__device__ __forceinline__ float sqrt_ap(float x) {
    float r; asm("sqrt.approx.f32 %0, %1;" : "=f"(r) : "f"(x)); return r;
}
__device__ __forceinline__ float rcp_ap(float x) {
    float r; asm("rcp.approx.f32 %0, %1;" : "=f"(r) : "f"(x)); return r;
}
__device__ __forceinline__ uint32_t f2h2(float a, float b) {
    __half2 h = __floats2half2_rn(a, b);
    return *reinterpret_cast<uint32_t*>(&h);
}
__device__ __forceinline__ uint32_t smem_u32(const void* p) {
    uint32_t a;
    asm("{ .reg .u64 t; cvta.to.shared.u64 t, %1; cvt.u32.u64 %0, t; }"
        : "=r"(a) : "l"(p));
    return a;
}
// swizzled word offset for half tiles: row r, 16B chunk j (0..7), word w (0..3)
__device__ __forceinline__ uint32_t swz(int r, int j, int w) {
    return r * 32 + ((j ^ (r & 7)) << 2) + w;
}

// ---------------------------------------------------------------------------
// Pass 1: Q = rownorm(1/(1+sqrt(max(||z||^2+||c||^2-2 z.c, 0)))) via fp16
// m16n8k16 mma.sync with ldmatrix fragment loads (6 LDSM.x4 per k-step vs
// 24 LDS.32). 4 warps x (32 rows x 64 cols), TM=128 rows/CTA, 5 CTAs/SM.
// Warp-local Q writeback (R16).
// ---------------------------------------------------------------------------
__global__ void __launch_bounds__(P1T, 5)
k_pass1(const float* __restrict__ z, const float* __restrict__ c,
        float* __restrict__ Q) {
    extern __shared__ __align__(16) uint32_t smw[];
    float* smf = (float*)smw;
    const uint32_t sb = smem_u32(smw);
    const int t = threadIdx.x;
    const int warp = t >> 5, lane = t & 31;
    const int g = lane >> 2, tig = lane & 3;

    const long long row0 = (long long)blockIdx.x * TM;

    // --- Stage z (128x64 fp32 -> fp16, swizzled), coalesced LDG.128 ---
    {
        const float4* zg = (const float4*)(z + row0 * NH);
#pragma unroll
        for (int k = 0; k < 16; ++k) {
            int i = t + k * P1T;
            float4 v = zg[i];
            int r = i >> 4, c4 = i & 15;
            uint32_t dst = WA + swz(r, c4 >> 1, 2 * (c4 & 1));
            *(uint2*)(smw + dst) = make_uint2(f2h2(v.x, v.y), f2h2(v.z, v.w));
        }
        const float4* cg = (const float4*)c;
#pragma unroll
        for (int k = 0; k < 8; ++k) {
            int i = t + k * P1T;
            float4 v = cg[i];
            int r = i >> 4, c4 = i & 15;
            uint32_t dst = WB + swz(r, c4 >> 1, 2 * (c4 & 1));
            *(uint2*)(smw + dst) = make_uint2(f2h2(v.x, v.y), f2h2(v.z, v.w));
        }
    }
    if (t < NK) smf[WCOL + t] = 0.f;
    __syncthreads();

    // --- ||z_r||^2 (threads 0..127) and ||c_n||^2 (threads 0..63) from tiles
    {
        float s = 0.f;
#pragma unroll
        for (int j = 0; j < 8; ++j) {
            uint4 q = *(const uint4*)(smw + WA + swz(t, j, 0));
            float2 f;
            f = __half22float2(*(__half2*)&q.x); s = fmaf(f.x,f.x,s); s = fmaf(f.y,f.y,s);
            f = __half22float2(*(__half2*)&q.y); s = fmaf(f.x,f.x,s); s = fmaf(f.y,f.y,s);
            f = __half22float2(*(__half2*)&q.z); s = fmaf(f.x,f.x,s); s = fmaf(f.y,f.y,s);
            f = __half22float2(*(__half2*)&q.w); s = fmaf(f.x,f.x,s); s = fmaf(f.y,f.y,s);
        }
        smf[WZ2 + t] = s;
        if (t < NK) {
            float sc = 0.f;
#pragma unroll
            for (int j = 0; j < 8; ++j) {
                uint4 q = *(const uint4*)(smw + WB + swz(t, j, 0));
                float2 f;
                f = __half22float2(*(__half2*)&q.x); sc = fmaf(f.x,f.x,sc); sc = fmaf(f.y,f.y,sc);
                f = __half22float2(*(__half2*)&q.y); sc = fmaf(f.x,f.x,sc); sc = fmaf(f.y,f.y,sc);
                f = __half22float2(*(__half2*)&q.z); sc = fmaf(f.x,f.x,sc); sc = fmaf(f.y,f.y,sc);
                f = __half22float2(*(__half2*)&q.w); sc = fmaf(f.x,f.x,sc); sc = fmaf(f.y,f.y,sc);
            }
            smf[WC2 + t] = sc;
        }
    }
    __syncthreads();

    // --- GEMM: warp w owns rows [w*32, w*32+32); 2 M-tiles x 8 N-tiles,
    //     4 K-steps of 16. Fragment loads via ldmatrix.x4.
    float d[8][2][4];
#pragma unroll
    for (int nt = 0; nt < 8; ++nt)
#pragma unroll
        for (int mt = 0; mt < 2; ++mt)
#pragma unroll
            for (int j = 0; j < 4; ++j) d[nt][mt][j] = 0.f;

    const int rowbase = warp * 32;
    const int l7 = lane & 7;            // row within 8-group / swizzle key
    const int l8 = (lane >> 3) & 1;     // A: +8 rows; B: k-half
    const int lhi = lane >> 4;          // A: k-half; B: nt parity

    // Per-lane base addresses (bytes). Row stride = 128 B.
    const uint32_t aRowByte = sb + WA * 4 + (rowbase + l8 * 8 + l7) * 128;
    const uint32_t bRowByte = sb + WB * 4 + l7 * 128;  // + nt*8*128 added below

#pragma unroll
    for (int ks = 0; ks < 4; ++ks) {
        const int chA = (2 * ks + lhi) ^ l7;   // swizzled chunk for A
        const int chB = (2 * ks + l8) ^ l7;    // swizzled chunk for B
        uint32_t a[2][4];
        ldsm_x4(a[0][0], a[0][1], a[0][2], a[0][3],
                aRowByte + (chA << 4));
        ldsm_x4(a[1][0], a[1][1], a[1][2], a[1][3],
                aRowByte + 16 * 128 + (chA << 4));

        uint32_t b[8][2];
#pragma unroll
        for (int p = 0; p < 4; ++p) {
            const int ntL = 2 * p + lhi;   // this lane addresses nt = ntL
            ldsm_x4(b[2 * p][0], b[2 * p][1], b[2 * p + 1][0], b[2 * p + 1][1],
                    bRowByte + ntL * 8 * 128 + (chB << 4));
        }
#pragma unroll
        for (int nt = 0; nt < 8; ++nt)
#pragma unroll
            for (int mt = 0; mt < 2; ++mt)
                mma_f16(d[nt][mt], a[mt][0], a[mt][1], a[mt][2], a[mt][3],
                        b[nt][0], b[nt][1]);
    }

    // --- Epilogue (in place). Thread owns rows rowbase + mt*16 + hr*8 + g,
    //     cols nt*8 + 2*tig + {0,1}.
    float z2r[4];
    z2r[0] = smf[WZ2 + rowbase + g];
    z2r[1] = smf[WZ2 + rowbase + g + 8];
    z2r[2] = smf[WZ2 + rowbase + g + 16];
    z2r[3] = smf[WZ2 + rowbase + g + 24];

    float rs[4] = {0.f, 0.f, 0.f, 0.f};
#pragma unroll
    for (int nt = 0; nt < 8; ++nt) {
        float c2a = smf[WC2 + nt * 8 + 2 * tig];
        float c2b = smf[WC2 + nt * 8 + 2 * tig + 1];
#pragma unroll
        for (int mt = 0; mt < 2; ++mt) {
#pragma unroll
            for (int hr = 0; hr < 2; ++hr) {
                int r = mt * 2 + hr;
                float da = fmaf(-2.f, d[nt][mt][hr * 2],     z2r[r] + c2a);
                float db = fmaf(-2.f, d[nt][mt][hr * 2 + 1], z2r[r] + c2b);
                float qa = rcp_ap(1.f + sqrt_ap(fmaxf(da, 0.f)));
                float qb = rcp_ap(1.f + sqrt_ap(fmaxf(db, 0.f)));
                d[nt][mt][hr * 2]     = qa;
                d[nt][mt][hr * 2 + 1] = qb;
                rs[r] += qa + qb;
            }
        }
    }
#pragma unroll
    for (int r = 0; r < 4; ++r) {
        rs[r] += __shfl_xor_sync(0xffffffffu, rs[r], 1);
        rs[r] += __shfl_xor_sync(0xffffffffu, rs[r], 2);
        rs[r] = rcp_ap(rs[r]);
    }

    __syncthreads();   // A/B tiles dead -> reuse smem as fp32 Q stage

    // Normalize; stage own warp's rows; fold colsum partials.
    float* stage = smf + WSTG;
#pragma unroll
    for (int nt = 0; nt < 8; ++nt) {
        float csa = 0.f, csb = 0.f;
#pragma unroll
        for (int mt = 0; mt < 2; ++mt) {
#pragma unroll
            for (int hr = 0; hr < 2; ++hr) {
                int r = mt * 2 + hr;
                float qa = d[nt][mt][hr * 2] * rs[r];
                float qb = d[nt][mt][hr * 2 + 1] * rs[r];
                csa += qa;
                csb += qb;
                float2 v = {qa, qb};
                *(float2*)(stage + (rowbase + mt * 16 + hr * 8 + g) * STRD +
                           nt * 8 + 2 * tig) = v;
            }
        }
        d[nt][0][0] = csa;
        d[nt][0][1] = csb;
    }
#pragma unroll
    for (int nt = 0; nt < 8; ++nt) {
#pragma unroll
        for (int j = 0; j < 2; ++j) {
            d[nt][0][j] += __shfl_xor_sync(0xffffffffu, d[nt][0][j], 4);
            d[nt][0][j] += __shfl_xor_sync(0xffffffffu, d[nt][0][j], 8);
            d[nt][0][j] += __shfl_xor_sync(0xffffffffu, d[nt][0][j], 16);
        }
    }
    if (g == 0) {
#pragma unroll
        for (int nt = 0; nt < 8; ++nt) {
            atomicAdd(&smf[WCOL + nt * 8 + 2 * tig], d[nt][0][0]);
            atomicAdd(&smf[WCOL + nt * 8 + 2 * tig + 1], d[nt][0][1]);
        }
    }
    __syncwarp();      // own warp's staged rows visible -> store immediately

    // WARP-LOCAL coalesced Q writeback: warp w stores rows [w*32, w*32+32).
    float4* out = (float4*)(Q + row0 * NH);
#pragma unroll
    for (int k = 0; k < 16; ++k) {
        int i = warp * 512 + lane + k * 32;
        int rr = i >> 4, cc = i & 15;
        out[i] = *(const float4*)(stage + rr * STRD + cc * 4);
    }

    __syncthreads();   // all warps' smem colsum atomics complete
    if (t < NK) atomicAdd(&g_colsum[t], smf[WCOL + t]);
}

// ---------------------------------------------------------------------------
// Pass 2: P = rownorm(Q^2 / colsum). 8 lanes per row, interleaved float4
// ownership -> every LDG/STG.128 covers whole 128B lines (minimal L1
// wavefronts; proven R14/R16 config). Last block re-zeroes colsum + ticket.
// ---------------------------------------------------------------------------
__global__ void __launch_bounds__(P2T)
k_pass2(const float* __restrict__ Q, float* __restrict__ P) {
    __shared__ float s_ic[NK];
    const int t = threadIdx.x;
    if (t < NK) s_ic[t] = rcp_ap(g_colsum[t]);
    __syncthreads();

    if (t == 0) {
        unsigned old = atomicAdd(&g_done, 1u);
        if (old == gridDim.x - 1) {
#pragma unroll
            for (int k = 0; k < NK; ++k) g_colsum[k] = 0.f;
            g_done = 0;
            __threadfence();
        }
    }

    const int warp = t >> 5, lane = t & 31;
    const int rsub = lane >> 3;     // row within the warp's 4-row group
    const int p8 = lane & 7;        // position within the 8-lane row group

    const long long row = (long long)blockIdx.x * 32 + warp * 4 + rsub;
    const float4* __restrict__ qr = (const float4*)(Q + row * NH);

    float4 ic0 = *(const float4*)(s_ic + 4 * p8);        // cols 4*p8..+3
    float4 ic1 = *(const float4*)(s_ic + 4 * p8 + 32);   // cols 4*p8+32..+3

    float4 v0 = qr[p8];        // fully coalesced: 8 lanes cover one 128B line
    float4 v1 = qr[p8 + 8];

    float4 q0, q1;
    q0.x = v0.x * v0.x * ic0.x;
    q0.y = v0.y * v0.y * ic0.y;
    q0.z = v0.z * v0.z * ic0.z;
    q0.w = v0.w * v0.w * ic0.w;
    q1.x = v1.x * v1.x * ic1.x;
    q1.y = v1.y * v1.y * ic1.y;
    q1.z = v1.z * v1.z * ic1.z;
    q1.w = v1.w * v1.w * ic1.w;

    float rs = ((q0.x + q0.y) + (q0.z + q0.w)) +
               ((q1.x + q1.y) + (q1.z + q1.w));
    rs += __shfl_xor_sync(0xffffffffu, rs, 1);
    rs += __shfl_xor_sync(0xffffffffu, rs, 2);
    rs += __shfl_xor_sync(0xffffffffu, rs, 4);
    const float inv = rcp_ap(rs);

    float4* __restrict__ po = (float4*)(P + row * NH);
    float4 o0, o1;
    o0.x = q0.x * inv; o0.y = q0.y * inv;
    o0.z = q0.z * inv; o0.w = q0.w * inv;
    o1.x = q1.x * inv; o1.y = q1.y * inv;
    o1.z = q1.z * inv; o1.w = q1.w * inv;
    po[p8] = o0;
    po[p8 + 8] = o1;
}

// ---------------------------------------------------------------------------
extern "C" void kernel_launch(void* const* d_in, const int* in_sizes, int n_in,
                              void* d_out, int out_size) {
    const float* z = (const float*)d_in[0];  // (BS, 64)
    const float* c = (const float*)d_in[1];  // (64, 64)
    const long long n_rows = (long long)in_sizes[0] / NH;

    float* Q = (float*)d_out;
    float* P = Q + n_rows * NK;

    static bool attr_set = false;
    if (!attr_set) {
        cudaFuncSetAttribute(k_pass1, cudaFuncAttributeMaxDynamicSharedMemorySize,
                             SMEM_BYTES);
        attr_set = true;
    }

    k_pass1<<<(int)(n_rows / TM), P1T, SMEM_BYTES>>>(z, c, Q);
    k_pass2<<<(int)(n_rows / 32), P2T>>>(Q, P);
}